// round 15
// baseline (speedup 1.0000x reference)
#include <cuda_runtime.h>

// Problem constants
#define MAXN 100000
#define MAXE 1600000
#define FIN 64
#define HID 64
#define NCLS 32
#define SCAN_B 512
#define MAXBLK 256   // max scan blocks (MAXN/SCAN_B = 196)

// ---------------- scratch (static device globals; no allocation) -------------
__device__ int      g_is64;
__device__ int      g_deg[MAXN];
__device__ int      g_rowtmp[MAXN];
__device__ int      g_bsum[MAXBLK];
__device__ int      g_boff[MAXBLK];
__device__ int      g_rowptr[MAXN + 1];
__device__ int      g_cursor[MAXN];
__device__ float    g_dinv[MAXN];
__device__ int2     g_csr[MAXE];          // {col, float_as_int(weight)}
__device__ float    g_bufA[MAXN * 64];
__device__ float    g_bufB[MAXN * 64];
__device__ float    g_bufC[MAXN * 64];

__device__ __forceinline__ float* selbuf(int s) {
    return (s == 0) ? g_bufA : (s == 1) ? g_bufB : g_bufC;
}

// 32-wide region selector: 0=bufA[0) (p2), 1=bufA[n*32) (p1), 2=bufB[0) (p0), 3=bufC[0)
__device__ __forceinline__ float* sel32(int s, int n) {
    if (s == 0) return g_bufA;
    if (s == 1) return g_bufA + (size_t)n * 32;
    if (s == 2) return g_bufB;
    return g_bufC;
}

__device__ __forceinline__ int edge_at(const void* ei, int e) {
    if (g_is64) return (int)((const long long*)ei)[e];
    return ((const int*)ei)[e];
}

// ---------------- threefry2x32 (20 rounds) -----------------------------------
__device__ __forceinline__ unsigned rotl32(unsigned x, int d) {
    return (x << d) | (x >> (32 - d));
}

__device__ __forceinline__ void tf20(unsigned k0, unsigned k1,
                                     unsigned c0, unsigned c1,
                                     unsigned& o0, unsigned& o1) {
    unsigned ks0 = k0, ks1 = k1, ks2 = 0x1BD11BDAu ^ k0 ^ k1;
    unsigned x0 = c0 + ks0, x1 = c1 + ks1;
#define TFR(r) { x0 += x1; x1 = rotl32(x1, (r)); x1 ^= x0; }
    TFR(13) TFR(15) TFR(26) TFR(6)
    x0 += ks1; x1 += ks2 + 1u;
    TFR(17) TFR(29) TFR(16) TFR(24)
    x0 += ks2; x1 += ks0 + 2u;
    TFR(13) TFR(15) TFR(26) TFR(6)
    x0 += ks0; x1 += ks1 + 3u;
    TFR(17) TFR(29) TFR(16) TFR(24)
    x0 += ks1; x1 += ks2 + 4u;
    TFR(13) TFR(15) TFR(26) TFR(6)
    x0 += ks2; x1 += ks0 + 5u;
#undef TFR
    o0 = x0; o1 = x1;
}

// dropout keep decision (JAX partitionable threefry, key(42))
__device__ __forceinline__ bool keep_elem(unsigned i) {
    unsigned o0, o1;
    tf20(0u, 42u, 0u, i, o0, o1);
    unsigned bits = o0 ^ o1;
    float u = __uint_as_float((bits >> 9) | 0x3F800000u) - 1.0f;
    return u < 0.5f;
}

// ---------------- setup kernels ----------------------------------------------
__global__ void zero_detect_kernel(const unsigned* __restrict__ w, int n) {
    int i = blockIdx.x * blockDim.x + threadIdx.x;
    if (i < n) g_deg[i] = 0;
    if (i == 0) {
        int is64 = 1;
        #pragma unroll
        for (int k = 0; k < 8; k++)
            if (w[2 * k + 1] != 0u) is64 = 0;
        g_is64 = is64;
    }
}

__global__ void deg_hist_kernel(const void* __restrict__ ei, int E) {
    int e = blockIdx.x * blockDim.x + threadIdx.x;
    if (e < E) {
        int r = edge_at(ei, e);
        atomicAdd(&g_deg[r], 1);
    }
}

__global__ void scan_local_kernel(int n) {
    __shared__ int sh[SCAN_B];
    int t = threadIdx.x;
    int i = blockIdx.x * SCAN_B + t;
    int v = (i < n) ? g_deg[i] : 0;
    sh[t] = v;
    __syncthreads();
    for (int off = 1; off < SCAN_B; off <<= 1) {
        int u = (t >= off) ? sh[t - off] : 0;
        __syncthreads();
        if (t >= off) sh[t] += u;
        __syncthreads();
    }
    if (i < n) g_rowtmp[i] = sh[t] - v;
    if (t == SCAN_B - 1) g_bsum[blockIdx.x] = sh[t];
}

__global__ void scan_bsums_kernel(int nb) {
    __shared__ int sh[MAXBLK];
    int t = threadIdx.x;
    int v = (t < nb) ? g_bsum[t] : 0;
    sh[t] = v;
    __syncthreads();
    for (int off = 1; off < MAXBLK; off <<= 1) {
        int u = (t >= off) ? sh[t - off] : 0;
        __syncthreads();
        if (t >= off) sh[t] += u;
        __syncthreads();
    }
    if (t < nb) g_boff[t] = sh[t] - v;
}

__global__ void scan_final_kernel(int n, int E) {
    int i = blockIdx.x * blockDim.x + threadIdx.x;
    if (i < n) {
        int v = g_rowtmp[i] + g_boff[i / SCAN_B];
        g_rowptr[i] = v;
        g_cursor[i] = v;
        int d = g_deg[i];
        g_dinv[i] = (d > 0) ? rsqrtf((float)d) : 0.0f;
    }
    if (i == 0) g_rowptr[n] = E;
}

__global__ void scatter_kernel(const void* __restrict__ ei, int E) {
    int e = blockIdx.x * blockDim.x + threadIdx.x;
    if (e < E) {
        int r = edge_at(ei, e);
        int c = edge_at(ei, E + e);
        int pos = atomicAdd(&g_cursor[r], 1);
        float w = -(g_dinv[r] * g_dinv[c]);
        g_csr[pos] = make_int2(c, __float_as_int(w));
    }
}

// ---------------- proj1: p0=x@(W0-W2)+b1 -> bufA; p1=x@W1 -> bufB; -----------
//                  p2=x@(2W2) -> bufC.   4 threads/node, 64 nodes/block.
__global__ void __launch_bounds__(256) proj1_kernel(
        const float* __restrict__ x,
        const float* __restrict__ W,
        const float* __restrict__ b, int n) {
    __shared__ float sw[3 * 64 * 64];  // 48KB: [W0-W2 | W1 | 2*W2]
    for (int i = threadIdx.x; i < 3 * 4096; i += 256) {
        int m = i >> 12, r = i & 4095;
        float v;
        if (m == 0)      v = W[r] - W[2 * 4096 + r];
        else if (m == 1) v = W[4096 + r];
        else             v = 2.0f * W[2 * 4096 + r];
        sw[i] = v;
    }
    __syncthreads();

    int node = blockIdx.x * 64 + (threadIdx.x >> 2);
    int jb   = (threadIdx.x & 3) * 16;
    if (node >= n) return;

    float aP[16], aQ[16], aR[16];
#pragma unroll
    for (int j = 0; j < 16; j++) { aP[j] = __ldg(&b[jb + j]); aQ[j] = 0.f; aR[j] = 0.f; }

    const float4* xp = (const float4*)(x + node * 64);
#pragma unroll
    for (int k4 = 0; k4 < 16; k4++) {
        float4 a4 = __ldg(&xp[k4]);
#pragma unroll
        for (int c = 0; c < 4; c++) {
            float av = ((const float*)&a4)[c];
            int k = k4 * 4 + c;
            const float* w0 = sw + k * 64 + jb;
            const float* w1 = sw + 4096 + k * 64 + jb;
            const float* w2 = sw + 8192 + k * 64 + jb;
#pragma unroll
            for (int jj = 0; jj < 16; jj++) {
                aP[jj] += av * w0[jj];
                aQ[jj] += av * w1[jj];
                aR[jj] += av * w2[jj];
            }
        }
    }
    float* opA = g_bufA + node * 64 + jb;
    float* opB = g_bufB + node * 64 + jb;
    float* opC = g_bufC + node * 64 + jb;
#pragma unroll
    for (int q = 0; q < 4; q++) {
        ((float4*)opA)[q] = make_float4(aP[q*4+0], aP[q*4+1], aP[q*4+2], aP[q*4+3]);
        ((float4*)opB)[q] = make_float4(aQ[q*4+0], aQ[q*4+1], aQ[q*4+2], aQ[q*4+3]);
        ((float4*)opC)[q] = make_float4(aR[q*4+0], aR[q*4+1], aR[q*4+2], aR[q*4+3]);
    }
}

// ---------------- SpMM64 (exact R8 inner loop; fused epilogues) --------------
// warp per node; float2 per lane (64 features).
// mode 1: dst = sum + other
// mode 2: dst = dropout(relu(sum + other))   (keeps hashed in gather shadow)
__global__ void spmm64_kernel(int src_sel, int oth_sel, int dst_sel,
                              int mode, int n) {
    const float* src = selbuf(src_sel);
    const float* oth = selbuf(oth_sel);
    float*       dst = selbuf(dst_sel);
    int node = (blockIdx.x * blockDim.x + threadIdx.x) >> 5;
    int lane = threadIdx.x & 31;
    if (node >= n) return;
    int start = g_rowptr[node];
    int end   = g_rowptr[node + 1];
    const float2* s2 = (const float2*)src;
    float ax = 0.f, ay = 0.f;

    // dropout keeps for this lane's two features (overlaps gather latency)
    bool k0 = true, k1 = true;
    if (mode == 2) {
        unsigned ib = (unsigned)node * 64u + 2u * (unsigned)lane;
        k0 = keep_elem(ib);
        k1 = keep_elem(ib + 1u);
    }

    for (int base = start; base < end; base += 32) {
        int idx = base + lane;
        int2 ce = make_int2(0, 0);
        if (idx < end) ce = g_csr[idx];
        int cnt = min(32, end - base);
        int j = 0;
        for (; j + 4 <= cnt; j += 4) {
            int   c0 = __shfl_sync(0xffffffffu, ce.x, j);
            int   c1 = __shfl_sync(0xffffffffu, ce.x, j + 1);
            int   c2 = __shfl_sync(0xffffffffu, ce.x, j + 2);
            int   c3 = __shfl_sync(0xffffffffu, ce.x, j + 3);
            float w0 = __int_as_float(__shfl_sync(0xffffffffu, ce.y, j));
            float w1 = __int_as_float(__shfl_sync(0xffffffffu, ce.y, j + 1));
            float w2 = __int_as_float(__shfl_sync(0xffffffffu, ce.y, j + 2));
            float w3 = __int_as_float(__shfl_sync(0xffffffffu, ce.y, j + 3));
            float2 v0 = __ldg(&s2[c0 * 32 + lane]);
            float2 v1 = __ldg(&s2[c1 * 32 + lane]);
            float2 v2 = __ldg(&s2[c2 * 32 + lane]);
            float2 v3 = __ldg(&s2[c3 * 32 + lane]);
            ax += w0 * v0.x; ay += w0 * v0.y;
            ax += w1 * v1.x; ay += w1 * v1.y;
            ax += w2 * v2.x; ay += w2 * v2.y;
            ax += w3 * v3.x; ay += w3 * v3.y;
        }
        for (; j < cnt; j++) {
            int   c = __shfl_sync(0xffffffffu, ce.x, j);
            float w = __int_as_float(__shfl_sync(0xffffffffu, ce.y, j));
            float2 v = __ldg(&s2[c * 32 + lane]);
            ax += w * v.x; ay += w * v.y;
        }
    }
    float2 o = ((const float2*)oth)[node * 32 + lane];
    ax += o.x;
    ay += o.y;
    if (mode == 2) {
        ax = k0 ? 2.0f * fmaxf(ax, 0.f) : 0.f;
        ay = k1 ? 2.0f * fmaxf(ay, 0.f) : 0.f;
    }
    ((float2*)dst)[node * 32 + lane] = make_float2(ax, ay);
}

// ---------------- proj2: from h (bufC): p2=h@(2W2) -> bufA[0,n*32); ----------
//                  p1=h@W1 -> bufA[n*32,..); p0=h@(W0-W2)+b2 -> bufB[0,n*32).
//                  2 threads/node, 128 nodes/block.
__global__ void __launch_bounds__(256) proj2_kernel(
        const float* __restrict__ W,
        const float* __restrict__ b, int n) {
    __shared__ float sw[3 * 64 * 32];  // 24KB: [W0-W2 | W1 | 2*W2]
    for (int i = threadIdx.x; i < 3 * 2048; i += 256) {
        int m = i >> 11, r = i & 2047;
        float v;
        if (m == 0)      v = W[r] - W[2 * 2048 + r];
        else if (m == 1) v = W[2048 + r];
        else             v = 2.0f * W[2 * 2048 + r];
        sw[i] = v;
    }
    __syncthreads();

    int node = blockIdx.x * 128 + (threadIdx.x >> 1);
    int jb   = (threadIdx.x & 1) * 16;
    if (node >= n) return;

    float aP[16], aQ[16], aR[16];
#pragma unroll
    for (int j = 0; j < 16; j++) { aP[j] = __ldg(&b[jb + j]); aQ[j] = 0.f; aR[j] = 0.f; }

    const float4* hp = (const float4*)(g_bufC + node * 64);
#pragma unroll
    for (int k4 = 0; k4 < 16; k4++) {
        float4 a4 = hp[k4];
#pragma unroll
        for (int c = 0; c < 4; c++) {
            float av = ((const float*)&a4)[c];
            int k = k4 * 4 + c;
            const float* w0 = sw + k * 32 + jb;
            const float* w1 = sw + 2048 + k * 32 + jb;
            const float* w2 = sw + 4096 + k * 32 + jb;
#pragma unroll
            for (int jj = 0; jj < 16; jj++) {
                aP[jj] += av * w0[jj];
                aQ[jj] += av * w1[jj];
                aR[jj] += av * w2[jj];
            }
        }
    }
    float* p2 = g_bufA + node * 32 + jb;
    float* p1 = g_bufA + (size_t)n * 32 + node * 32 + jb;
    float* p0 = g_bufB + node * 32 + jb;
#pragma unroll
    for (int q = 0; q < 4; q++) {
        ((float4*)p2)[q] = make_float4(aR[q*4+0], aR[q*4+1], aR[q*4+2], aR[q*4+3]);
        ((float4*)p1)[q] = make_float4(aQ[q*4+0], aQ[q*4+1], aQ[q*4+2], aQ[q*4+3]);
        ((float4*)p0)[q] = make_float4(aP[q*4+0], aP[q*4+1], aP[q*4+2], aP[q*4+3]);
    }
}

// ---------------- SpMM32: 32-wide propagate (layer 2) -------------------------
// warp per node; 1 float per lane. dst = sum + other, optionally log_softmax
// over the warp's 32 lanes writing straight to ext_out.
__global__ void spmm32_kernel(int src_sel, int oth_sel, int dst_sel,
                              float* __restrict__ ext_out, int do_lsm, int n) {
    const float* src = sel32(src_sel, n);
    const float* oth = sel32(oth_sel, n);
    int node = (blockIdx.x * blockDim.x + threadIdx.x) >> 5;
    int lane = threadIdx.x & 31;
    if (node >= n) return;
    int start = g_rowptr[node];
    int end   = g_rowptr[node + 1];
    float acc = 0.f;

    for (int base = start; base < end; base += 32) {
        int idx = base + lane;
        int2 ce = make_int2(0, 0);
        if (idx < end) ce = g_csr[idx];
        int cnt = min(32, end - base);
        int j = 0;
        for (; j + 4 <= cnt; j += 4) {
            int   c0 = __shfl_sync(0xffffffffu, ce.x, j);
            int   c1 = __shfl_sync(0xffffffffu, ce.x, j + 1);
            int   c2 = __shfl_sync(0xffffffffu, ce.x, j + 2);
            int   c3 = __shfl_sync(0xffffffffu, ce.x, j + 3);
            float w0 = __int_as_float(__shfl_sync(0xffffffffu, ce.y, j));
            float w1 = __int_as_float(__shfl_sync(0xffffffffu, ce.y, j + 1));
            float w2 = __int_as_float(__shfl_sync(0xffffffffu, ce.y, j + 2));
            float w3 = __int_as_float(__shfl_sync(0xffffffffu, ce.y, j + 3));
            float v0 = __ldg(&src[c0 * 32 + lane]);
            float v1 = __ldg(&src[c1 * 32 + lane]);
            float v2 = __ldg(&src[c2 * 32 + lane]);
            float v3 = __ldg(&src[c3 * 32 + lane]);
            acc += w0 * v0;
            acc += w1 * v1;
            acc += w2 * v2;
            acc += w3 * v3;
        }
        for (; j < cnt; j++) {
            int   c = __shfl_sync(0xffffffffu, ce.x, j);
            float w = __int_as_float(__shfl_sync(0xffffffffu, ce.y, j));
            acc += w * __ldg(&src[c * 32 + lane]);
        }
    }
    float val = acc + oth[node * 32 + lane];
    if (do_lsm) {
        // log_softmax across the warp's 32 lanes (= 32 classes)
        float m = val;
#pragma unroll
        for (int d = 16; d > 0; d >>= 1)
            m = fmaxf(m, __shfl_xor_sync(0xffffffffu, m, d));
        float e = expf(val - m);
        float s = e;
#pragma unroll
        for (int d = 16; d > 0; d >>= 1)
            s += __shfl_xor_sync(0xffffffffu, s, d);
        ext_out[node * 32 + lane] = val - (m + logf(s));
    } else {
        float* dst = sel32(dst_sel, n);
        dst[node * 32 + lane] = val;
    }
}

// ---------------- launch ------------------------------------------------------
extern "C" void kernel_launch(void* const* d_in, const int* in_sizes, int n_in,
                              void* d_out, int out_size) {
    const float* x  = (const float*)d_in[0];
    const void*  ei = d_in[1];
    const float* W1 = (const float*)d_in[2];
    const float* b1 = (const float*)d_in[3];
    const float* W2 = (const float*)d_in[4];
    const float* b2 = (const float*)d_in[5];
    float* out = (float*)d_out;

    int n = in_sizes[0] / FIN;       // 100000
    int E = in_sizes[1] / 2;         // 1600000

    const int T = 256;
    int gN  = (n + T - 1) / T;
    int gE  = (E + T - 1) / T;
    int gW  = (n * 32 + T - 1) / T;        // warp-per-node grids
    int gP1 = (n + 63) / 64;
    int gP2 = (n + 127) / 128;
    int nb  = (n + SCAN_B - 1) / SCAN_B;

    // ---- CSR + norm setup ----
    zero_detect_kernel<<<gN, T>>>((const unsigned*)ei, n);
    deg_hist_kernel<<<gE, T>>>(ei, E);
    scan_local_kernel<<<nb, SCAN_B>>>(n);
    scan_bsums_kernel<<<1, MAXBLK>>>(nb);
    scan_final_kernel<<<gN, T>>>(n, E);
    scatter_kernel<<<gE, T>>>(ei, E);

    // ---- layer 1 (project-then-propagate) ----
    // p0 = x@(W0-W2)+b1 -> bufA ; p1 = x@W1 -> bufB ; p2 = x@(2W2) -> bufC
    proj1_kernel<<<gP1, T>>>(x, W1, b1, n);
    // s = L*p2 + p1            -> bufB
    spmm64_kernel<<<gW, T>>>(2, 1, 1, 1, n);
    // h = dropout(relu(L*s + p0)) -> bufC
    spmm64_kernel<<<gW, T>>>(1, 0, 2, 2, n);

    // ---- layer 2 (project-then-propagate, 32-wide) ----
    // p2 = h@(2W2) -> bufA[0,n*32) ; p1 = h@W1 -> bufA[n*32,..) ;
    // p0 = h@(W0-W2)+b2 -> bufB[0,n*32)
    proj2_kernel<<<gP2, T>>>(W2, b2, n);
    // s2 = L*p2 + p1 -> bufC[0,n*32)
    spmm32_kernel<<<gW, T>>>(0, 1, 3, nullptr, 0, n);
    // out = log_softmax(L*s2 + p0)
    spmm32_kernel<<<gW, T>>>(3, 2, -1, out, 1, n);
}

// round 16
// speedup vs baseline: 2.0028x; 2.0028x over previous
#include <cuda_runtime.h>

// Problem constants
#define MAXN 100000
#define MAXE 1600000
#define FIN 64
#define HID 64
#define NCLS 32
#define SCAN_B 512
#define MAXBLK 256   // max scan blocks (MAXN/SCAN_B = 196)

// ---------------- scratch (static device globals; no allocation) -------------
__device__ int      g_is64;
__device__ int      g_deg[MAXN];
__device__ int      g_rowtmp[MAXN];
__device__ int      g_bsum[MAXBLK];
__device__ int      g_boff[MAXBLK];
__device__ int      g_rowptr[MAXN + 1];
__device__ int      g_cursor[MAXN];
__device__ float    g_dinv[MAXN];
__device__ int2     g_csr[MAXE];          // {col, float_as_int(weight)}
__device__ float    g_bufA[MAXN * 64];
__device__ float    g_bufB[MAXN * 64];
__device__ float    g_bufC[MAXN * 64];

__device__ __forceinline__ float* selbuf(int s) {
    return (s == 0) ? g_bufA : (s == 1) ? g_bufB : g_bufC;
}

// 32-wide region selector for layer 2:
// 0 = bufA[0)        (p2)
// 1 = bufA + n*32    (p1)
// 2 = bufB[0)        (p0)
// 3 = bufB + n*32    (s2 scratch)
__device__ __forceinline__ float* sel32(int s, int n) {
    if (s == 0) return g_bufA;
    if (s == 1) return g_bufA + (size_t)n * 32;
    if (s == 2) return g_bufB;
    return g_bufB + (size_t)n * 32;
}

__device__ __forceinline__ int edge_at(const void* ei, int e) {
    if (g_is64) return (int)((const long long*)ei)[e];
    return ((const int*)ei)[e];
}

// ---------------- threefry2x32 (20 rounds) -----------------------------------
__device__ __forceinline__ unsigned rotl32(unsigned x, int d) {
    return (x << d) | (x >> (32 - d));
}

__device__ __forceinline__ void tf20(unsigned k0, unsigned k1,
                                     unsigned c0, unsigned c1,
                                     unsigned& o0, unsigned& o1) {
    unsigned ks0 = k0, ks1 = k1, ks2 = 0x1BD11BDAu ^ k0 ^ k1;
    unsigned x0 = c0 + ks0, x1 = c1 + ks1;
#define TFR(r) { x0 += x1; x1 = rotl32(x1, (r)); x1 ^= x0; }
    TFR(13) TFR(15) TFR(26) TFR(6)
    x0 += ks1; x1 += ks2 + 1u;
    TFR(17) TFR(29) TFR(16) TFR(24)
    x0 += ks2; x1 += ks0 + 2u;
    TFR(13) TFR(15) TFR(26) TFR(6)
    x0 += ks0; x1 += ks1 + 3u;
    TFR(17) TFR(29) TFR(16) TFR(24)
    x0 += ks1; x1 += ks2 + 4u;
    TFR(13) TFR(15) TFR(26) TFR(6)
    x0 += ks2; x1 += ks0 + 5u;
#undef TFR
    o0 = x0; o1 = x1;
}

// dropout keep decision (JAX partitionable threefry, key(42))
__device__ __forceinline__ bool keep_elem(unsigned i) {
    unsigned o0, o1;
    tf20(0u, 42u, 0u, i, o0, o1);
    unsigned bits = o0 ^ o1;
    float u = __uint_as_float((bits >> 9) | 0x3F800000u) - 1.0f;
    return u < 0.5f;
}

// ---------------- setup kernels ----------------------------------------------
__global__ void zero_detect_kernel(const unsigned* __restrict__ w, int n) {
    int i = blockIdx.x * blockDim.x + threadIdx.x;
    if (i < n) g_deg[i] = 0;
    if (i == 0) {
        int is64 = 1;
        #pragma unroll
        for (int k = 0; k < 8; k++)
            if (w[2 * k + 1] != 0u) is64 = 0;
        g_is64 = is64;
    }
}

__global__ void deg_hist_kernel(const void* __restrict__ ei, int E) {
    int e = blockIdx.x * blockDim.x + threadIdx.x;
    if (e < E) {
        int r = edge_at(ei, e);
        atomicAdd(&g_deg[r], 1);
    }
}

__global__ void scan_local_kernel(int n) {
    __shared__ int sh[SCAN_B];
    int t = threadIdx.x;
    int i = blockIdx.x * SCAN_B + t;
    int v = (i < n) ? g_deg[i] : 0;
    sh[t] = v;
    __syncthreads();
    for (int off = 1; off < SCAN_B; off <<= 1) {
        int u = (t >= off) ? sh[t - off] : 0;
        __syncthreads();
        if (t >= off) sh[t] += u;
        __syncthreads();
    }
    if (i < n) g_rowtmp[i] = sh[t] - v;
    if (t == SCAN_B - 1) g_bsum[blockIdx.x] = sh[t];
}

__global__ void scan_bsums_kernel(int nb) {
    __shared__ int sh[MAXBLK];
    int t = threadIdx.x;
    int v = (t < nb) ? g_bsum[t] : 0;
    sh[t] = v;
    __syncthreads();
    for (int off = 1; off < MAXBLK; off <<= 1) {
        int u = (t >= off) ? sh[t - off] : 0;
        __syncthreads();
        if (t >= off) sh[t] += u;
        __syncthreads();
    }
    if (t < nb) g_boff[t] = sh[t] - v;
}

__global__ void scan_final_kernel(int n, int E) {
    int i = blockIdx.x * blockDim.x + threadIdx.x;
    if (i < n) {
        int v = g_rowtmp[i] + g_boff[i / SCAN_B];
        g_rowptr[i] = v;
        g_cursor[i] = v;
        int d = g_deg[i];
        g_dinv[i] = (d > 0) ? rsqrtf((float)d) : 0.0f;
    }
    if (i == 0) g_rowptr[n] = E;
}

__global__ void scatter_kernel(const void* __restrict__ ei, int E) {
    int e = blockIdx.x * blockDim.x + threadIdx.x;
    if (e < E) {
        int r = edge_at(ei, e);
        int c = edge_at(ei, E + e);
        int pos = atomicAdd(&g_cursor[r], 1);
        float w = -(g_dinv[r] * g_dinv[c]);
        g_csr[pos] = make_int2(c, __float_as_int(w));
    }
}

// ---------------- SpMM64 (exact R8 inner loop) --------------------------------
// warp per node; cooperative edge-metadata load + shfl broadcast; 4-deep gathers
__global__ void spmm_kernel(const float* __restrict__ ext_src, int src_sel,
                            int dst_sel,
                            const float* __restrict__ ext_other, int other_sel,
                            int mode, int n) {
    const float* src = (src_sel < 0) ? ext_src : selbuf(src_sel);
    float*       dst = selbuf(dst_sel);
    int node = (blockIdx.x * blockDim.x + threadIdx.x) >> 5;
    int lane = threadIdx.x & 31;
    if (node >= n) return;
    int start = g_rowptr[node];
    int end   = g_rowptr[node + 1];
    const float2* s2 = (const float2*)src;
    float ax = 0.f, ay = 0.f;

    for (int base = start; base < end; base += 32) {
        int idx = base + lane;
        int2 ce = make_int2(0, 0);
        if (idx < end) ce = g_csr[idx];
        int cnt = min(32, end - base);
        int j = 0;
        for (; j + 4 <= cnt; j += 4) {
            int   c0 = __shfl_sync(0xffffffffu, ce.x, j);
            int   c1 = __shfl_sync(0xffffffffu, ce.x, j + 1);
            int   c2 = __shfl_sync(0xffffffffu, ce.x, j + 2);
            int   c3 = __shfl_sync(0xffffffffu, ce.x, j + 3);
            float w0 = __int_as_float(__shfl_sync(0xffffffffu, ce.y, j));
            float w1 = __int_as_float(__shfl_sync(0xffffffffu, ce.y, j + 1));
            float w2 = __int_as_float(__shfl_sync(0xffffffffu, ce.y, j + 2));
            float w3 = __int_as_float(__shfl_sync(0xffffffffu, ce.y, j + 3));
            float2 v0 = __ldg(&s2[c0 * 32 + lane]);
            float2 v1 = __ldg(&s2[c1 * 32 + lane]);
            float2 v2 = __ldg(&s2[c2 * 32 + lane]);
            float2 v3 = __ldg(&s2[c3 * 32 + lane]);
            ax += w0 * v0.x; ay += w0 * v0.y;
            ax += w1 * v1.x; ay += w1 * v1.y;
            ax += w2 * v2.x; ay += w2 * v2.y;
            ax += w3 * v3.x; ay += w3 * v3.y;
        }
        for (; j < cnt; j++) {
            int   c = __shfl_sync(0xffffffffu, ce.x, j);
            float w = __int_as_float(__shfl_sync(0xffffffffu, ce.y, j));
            float2 v = __ldg(&s2[c * 32 + lane]);
            ax += w * v.x; ay += w * v.y;
        }
    }
    if (mode) {
        const float* oth = (other_sel < 0) ? ext_other : selbuf(other_sel);
        float2 o = ((const float2*)oth)[node * 32 + lane];
        ax = 2.0f * ax - o.x;
        ay = 2.0f * ay - o.y;
    }
    ((float2*)dst)[node * 32 + lane] = make_float2(ax, ay);
}

// ---------------- GEMM1: h = dropout(relu(x@W0 + A@W1 + B@W2 + b)) -----------
// (exact R8 form) 256 threads; 2 nodes/thread; 128 nodes/block
__global__ void __launch_bounds__(256) gemm1_kernel(
        const float* __restrict__ x,
        const float* __restrict__ W,
        const float* __restrict__ b, int n) {
    __shared__ float sw[3 * 64 * 64];  // 48KB
    for (int i = threadIdx.x; i < 3 * 64 * 64 / 4; i += 256)
        ((float4*)sw)[i] = ((const float4*)W)[i];
    __syncthreads();

    int local = threadIdx.x >> 2;              // 0..63
    int jb    = (threadIdx.x & 3) * 16;
    int node0 = blockIdx.x * 128 + local;
    int node1 = node0 + 64;
    if (node0 >= n) return;
    bool v1 = (node1 < n);
    int nd1 = v1 ? node1 : node0;

    float acc0[16], acc1[16];
#pragma unroll
    for (int j = 0; j < 16; j++) { acc0[j] = __ldg(&b[jb + j]); acc1[j] = acc0[j]; }

    const float* in0[3] = { x + node0 * 64, g_bufA + node0 * 64, g_bufB + node0 * 64 };
    const float* in1[3] = { x + nd1 * 64,   g_bufA + nd1 * 64,   g_bufB + nd1 * 64 };
#pragma unroll
    for (int m = 0; m < 3; m++) {
        const float4* ip0 = (const float4*)in0[m];
        const float4* ip1 = (const float4*)in1[m];
        const float* wm = sw + m * 4096 + jb;
#pragma unroll
        for (int k4 = 0; k4 < 16; k4++) {
            float4 a4 = __ldg(&ip0[k4]);
            float4 b4 = __ldg(&ip1[k4]);
            const float* wr = wm + (k4 * 4) * 64;
#pragma unroll
            for (int c = 0; c < 4; c++) {
                float av = ((const float*)&a4)[c];
                float bv = ((const float*)&b4)[c];
                const float* wrow = wr + c * 64;
#pragma unroll
                for (int jj = 0; jj < 16; jj++) {
                    float wv = wrow[jj];
                    acc0[jj] += av * wv;
                    acc1[jj] += bv * wv;
                }
            }
        }
    }
    // relu + dropout fused epilogue
    {
        float* op = g_bufC + node0 * 64 + jb;
        int ib = node0 * 64 + jb;
#pragma unroll
        for (int q = 0; q < 4; q++) {
            float4 o;
            o.x = keep_elem(ib + q * 4 + 0) ? 2.0f * fmaxf(acc0[q * 4 + 0], 0.f) : 0.f;
            o.y = keep_elem(ib + q * 4 + 1) ? 2.0f * fmaxf(acc0[q * 4 + 1], 0.f) : 0.f;
            o.z = keep_elem(ib + q * 4 + 2) ? 2.0f * fmaxf(acc0[q * 4 + 2], 0.f) : 0.f;
            o.w = keep_elem(ib + q * 4 + 3) ? 2.0f * fmaxf(acc0[q * 4 + 3], 0.f) : 0.f;
            ((float4*)op)[q] = o;
        }
    }
    if (v1) {
        float* op = g_bufC + node1 * 64 + jb;
        int ib = node1 * 64 + jb;
#pragma unroll
        for (int q = 0; q < 4; q++) {
            float4 o;
            o.x = keep_elem(ib + q * 4 + 0) ? 2.0f * fmaxf(acc1[q * 4 + 0], 0.f) : 0.f;
            o.y = keep_elem(ib + q * 4 + 1) ? 2.0f * fmaxf(acc1[q * 4 + 1], 0.f) : 0.f;
            o.z = keep_elem(ib + q * 4 + 2) ? 2.0f * fmaxf(acc1[q * 4 + 2], 0.f) : 0.f;
            o.w = keep_elem(ib + q * 4 + 3) ? 2.0f * fmaxf(acc1[q * 4 + 3], 0.f) : 0.f;
            ((float4*)op)[q] = o;
        }
    }
}

// ---------------- proj2: h (bufC) -> p0,p1,p2 (32-wide), 2 nodes/thread ------
// p0 = h@(W0-W2)+b2 -> bufB[0)  ; p1 = h@W1 -> bufA+n*32 ; p2 = h@(2W2) -> bufA[0)
// 256 threads; 2 threads/node-column (jb 0/16); 2 nodes per thread; 256 nodes/block
__global__ void __launch_bounds__(256) proj2_kernel(
        const float* __restrict__ W,
        const float* __restrict__ b, int n) {
    __shared__ float sw[3 * 64 * 32];  // 24KB: [W0-W2 | W1 | 2*W2]
    for (int i = threadIdx.x; i < 3 * 2048; i += 256) {
        int m = i >> 11, r = i & 2047;
        float v;
        if (m == 0)      v = W[r] - W[2 * 2048 + r];
        else if (m == 1) v = W[2048 + r];
        else             v = 2.0f * W[2 * 2048 + r];
        sw[i] = v;
    }
    __syncthreads();

    int local = threadIdx.x >> 1;              // 0..127
    int jb    = (threadIdx.x & 1) * 16;
    int node0 = blockIdx.x * 256 + local;
    int node1 = node0 + 128;
    bool v0 = (node0 < n);
    bool v1 = (node1 < n);
    if (!v0) return;
    int nd1 = v1 ? node1 : node0;

    float P0[16], Q0[16], R0[16], P1[16], Q1[16], R1[16];
#pragma unroll
    for (int j = 0; j < 16; j++) {
        float bb = __ldg(&b[jb + j]);
        P0[j] = bb; Q0[j] = 0.f; R0[j] = 0.f;
        P1[j] = bb; Q1[j] = 0.f; R1[j] = 0.f;
    }

    const float4* h0 = (const float4*)(g_bufC + node0 * 64);
    const float4* h1 = (const float4*)(g_bufC + nd1 * 64);
#pragma unroll
    for (int k4 = 0; k4 < 16; k4++) {
        float4 a4 = h0[k4];
        float4 b4 = h1[k4];
#pragma unroll
        for (int c = 0; c < 4; c++) {
            float av = ((const float*)&a4)[c];
            float bv = ((const float*)&b4)[c];
            int k = k4 * 4 + c;
            const float* w0 = sw + k * 32 + jb;
            const float* w1 = sw + 2048 + k * 32 + jb;
            const float* w2 = sw + 4096 + k * 32 + jb;
#pragma unroll
            for (int jj = 0; jj < 16; jj++) {
                float wv0 = w0[jj], wv1 = w1[jj], wv2 = w2[jj];
                P0[jj] += av * wv0; P1[jj] += bv * wv0;
                Q0[jj] += av * wv1; Q1[jj] += bv * wv1;
                R0[jj] += av * wv2; R1[jj] += bv * wv2;
            }
        }
    }
    size_t off1 = (size_t)n * 32;
    {
        float* p0 = g_bufB + node0 * 32 + jb;
        float* p1 = g_bufA + off1 + node0 * 32 + jb;
        float* p2 = g_bufA + node0 * 32 + jb;
#pragma unroll
        for (int q = 0; q < 4; q++) {
            ((float4*)p0)[q] = make_float4(P0[q*4+0], P0[q*4+1], P0[q*4+2], P0[q*4+3]);
            ((float4*)p1)[q] = make_float4(Q0[q*4+0], Q0[q*4+1], Q0[q*4+2], Q0[q*4+3]);
            ((float4*)p2)[q] = make_float4(R0[q*4+0], R0[q*4+1], R0[q*4+2], R0[q*4+3]);
        }
    }
    if (v1) {
        float* p0 = g_bufB + node1 * 32 + jb;
        float* p1 = g_bufA + off1 + node1 * 32 + jb;
        float* p2 = g_bufA + node1 * 32 + jb;
#pragma unroll
        for (int q = 0; q < 4; q++) {
            ((float4*)p0)[q] = make_float4(P1[q*4+0], P1[q*4+1], P1[q*4+2], P1[q*4+3]);
            ((float4*)p1)[q] = make_float4(Q1[q*4+0], Q1[q*4+1], Q1[q*4+2], Q1[q*4+3]);
            ((float4*)p2)[q] = make_float4(R1[q*4+0], R1[q*4+1], R1[q*4+2], R1[q*4+3]);
        }
    }
}

// ---------------- SpMM32: 32-wide propagate (layer 2) -------------------------
// warp per node; 1 float per lane; same gather structure as spmm64.
// dst = L*src + oth; if do_lsm, apply warp-level log_softmax and write ext_out.
__global__ void spmm32_kernel(int src_sel, int oth_sel, int dst_sel,
                              float* __restrict__ ext_out, int do_lsm, int n) {
    const float* src = sel32(src_sel, n);
    const float* oth = sel32(oth_sel, n);
    int node = (blockIdx.x * blockDim.x + threadIdx.x) >> 5;
    int lane = threadIdx.x & 31;
    if (node >= n) return;
    int start = g_rowptr[node];
    int end   = g_rowptr[node + 1];
    float acc = 0.f;

    for (int base = start; base < end; base += 32) {
        int idx = base + lane;
        int2 ce = make_int2(0, 0);
        if (idx < end) ce = g_csr[idx];
        int cnt = min(32, end - base);
        int j = 0;
        for (; j + 4 <= cnt; j += 4) {
            int   c0 = __shfl_sync(0xffffffffu, ce.x, j);
            int   c1 = __shfl_sync(0xffffffffu, ce.x, j + 1);
            int   c2 = __shfl_sync(0xffffffffu, ce.x, j + 2);
            int   c3 = __shfl_sync(0xffffffffu, ce.x, j + 3);
            float w0 = __int_as_float(__shfl_sync(0xffffffffu, ce.y, j));
            float w1 = __int_as_float(__shfl_sync(0xffffffffu, ce.y, j + 1));
            float w2 = __int_as_float(__shfl_sync(0xffffffffu, ce.y, j + 2));
            float w3 = __int_as_float(__shfl_sync(0xffffffffu, ce.y, j + 3));
            float v0 = __ldg(&src[c0 * 32 + lane]);
            float v1 = __ldg(&src[c1 * 32 + lane]);
            float v2 = __ldg(&src[c2 * 32 + lane]);
            float v3 = __ldg(&src[c3 * 32 + lane]);
            acc += w0 * v0;
            acc += w1 * v1;
            acc += w2 * v2;
            acc += w3 * v3;
        }
        for (; j < cnt; j++) {
            int   c = __shfl_sync(0xffffffffu, ce.x, j);
            float w = __int_as_float(__shfl_sync(0xffffffffu, ce.y, j));
            acc += w * __ldg(&src[c * 32 + lane]);
        }
    }
    float val = acc + oth[node * 32 + lane];
    if (do_lsm) {
        float m = val;
#pragma unroll
        for (int d = 16; d > 0; d >>= 1)
            m = fmaxf(m, __shfl_xor_sync(0xffffffffu, m, d));
        float e = expf(val - m);
        float s = e;
#pragma unroll
        for (int d = 16; d > 0; d >>= 1)
            s += __shfl_xor_sync(0xffffffffu, s, d);
        ext_out[node * 32 + lane] = val - (m + logf(s));
    } else {
        float* dst = sel32(dst_sel, n);
        dst[node * 32 + lane] = val;
    }
}

// ---------------- launch ------------------------------------------------------
extern "C" void kernel_launch(void* const* d_in, const int* in_sizes, int n_in,
                              void* d_out, int out_size) {
    const float* x  = (const float*)d_in[0];
    const void*  ei = d_in[1];
    const float* W1 = (const float*)d_in[2];
    const float* b1 = (const float*)d_in[3];
    const float* W2 = (const float*)d_in[4];
    const float* b2 = (const float*)d_in[5];
    float* out = (float*)d_out;

    int n = in_sizes[0] / FIN;       // 100000
    int E = in_sizes[1] / 2;         // 1600000

    const int T = 256;
    int gN  = (n + T - 1) / T;
    int gE  = (E + T - 1) / T;
    int gW  = (n * 32 + T - 1) / T;        // warp-per-node grids
    int gG1 = (n + 127) / 128;
    int gP2 = (n + 255) / 256;
    int nb  = (n + SCAN_B - 1) / SCAN_B;

    // ---- CSR + norm setup (unchanged R8) ----
    zero_detect_kernel<<<gN, T>>>((const unsigned*)ei, n);
    deg_hist_kernel<<<gE, T>>>(ei, E);
    scan_local_kernel<<<nb, SCAN_B>>>(n);
    scan_bsums_kernel<<<1, MAXBLK>>>(nb);
    scan_final_kernel<<<gN, T>>>(n, E);
    scatter_kernel<<<gE, T>>>(ei, E);

    // ---- layer 1 (unchanged R8) ----
    spmm_kernel<<<gW, T>>>(x, -1, 0, nullptr, -2, 0, n);        // Tx1 -> bufA
    spmm_kernel<<<gW, T>>>(nullptr, 0, 1, x, -1, 1, n);         // Tx2 -> bufB
    gemm1_kernel<<<gG1, T>>>(x, W1, b1, n);                     // h   -> bufC

    // ---- layer 2 (project-then-propagate, 32-wide) ----
    proj2_kernel<<<gP2, T>>>(W2, b2, n);                        // p0,p1,p2
    spmm32_kernel<<<gW, T>>>(0, 1, 3, nullptr, 0, n);           // s2 = L*p2 + p1
    spmm32_kernel<<<gW, T>>>(3, 2, -1, out, 1, n);              // out = lsm(L*s2 + p0)
}